// round 13
// baseline (speedup 1.0000x reference)
#include <cuda_runtime.h>
#include <cuda_fp16.h>
#include <cstdint>

#define BB    4
#define TT    256
#define UU    128
#define EDIM  512
#define DDIM  640
#define JDIM  512
#define VDIM  1024

#define BK 64

// scratch (__device__ globals; no allocation allowed)
__device__ __half g_encp [BB*TT*JDIM];
__device__ __half g_decp [BB*UU*JDIM];
__device__ __half g_WencT[JDIM*EDIM];
__device__ __half g_WdecT[JDIM*DDIM];
__device__ __half g_WoutT[VDIM*JDIM];

__device__ __forceinline__ uint32_t smem_u32(const void* p) {
    uint32_t a;
    asm("{ .reg .u64 t; cvta.to.shared.u64 t, %1; cvt.u32.u64 %0, t; }" : "=r"(a) : "l"(p));
    return a;
}
__device__ __forceinline__ void ldsm_x4(uint32_t& r0, uint32_t& r1, uint32_t& r2, uint32_t& r3,
                                        uint32_t a) {
    asm volatile("ldmatrix.sync.aligned.m8n8.x4.shared.b16 {%0,%1,%2,%3}, [%4];"
                 : "=r"(r0), "=r"(r1), "=r"(r2), "=r"(r3) : "r"(a));
}
__device__ __forceinline__ void mma16816(float* c, const uint32_t* a, const uint32_t* b) {
    asm volatile("mma.sync.aligned.m16n8k16.row.col.f32.f16.f16.f32 "
                 "{%0,%1,%2,%3}, {%4,%5,%6,%7}, {%8,%9}, {%0,%1,%2,%3};"
                 : "+f"(c[0]), "+f"(c[1]), "+f"(c[2]), "+f"(c[3])
                 : "r"(a[0]), "r"(a[1]), "r"(a[2]), "r"(a[3]), "r"(b[0]), "r"(b[1]));
}
#define CP_ASYNC16(dst, src) \
    asm volatile("cp.async.cg.shared.global [%0], [%1], 16;" :: "r"(dst), "l"(src) : "memory")
#define CP_COMMIT() asm volatile("cp.async.commit_group;" ::: "memory")
#define CP_WAIT0()  asm volatile("cp.async.wait_group 0;" ::: "memory")

__device__ __forceinline__ uint32_t pack_h2(float lo, float hi) {
    __half2 h = __floats2half2_rn(lo, hi);
    return reinterpret_cast<uint32_t&>(h);
}
__device__ __forceinline__ uint32_t tanh_add_h2(uint32_t a, uint32_t b) {
    __half2 s = __hadd2(reinterpret_cast<__half2&>(a), reinterpret_cast<__half2&>(b));
    uint32_t su = reinterpret_cast<uint32_t&>(s), r;
    asm("tanh.approx.f16x2 %0, %1;" : "=r"(r) : "r"(su));
    return r;
}

// 32x32 warp-tile chunk (proj kernel)
__device__ __forceinline__ void mma_chunk32(uint32_t As, uint32_t Bs, int wm, int wn,
                                            int lane, float acc[2][4][4]) {
    const int arow = wm + (lane & 15);
    const int hi   = lane >> 4;
    const int brow = wn + ((lane >> 3) & 1) * 8 + (lane & 7);
    #pragma unroll
    for (int s = 0; s < 4; ++s) {
        const int g = s * 2 + hi;
        uint32_t a[2][4];
        #pragma unroll
        for (int t = 0; t < 2; ++t) {
            const int m = arow + t * 16;
            ldsm_x4(a[t][0], a[t][1], a[t][2], a[t][3], As + m * 128 + ((g ^ (m & 7)) << 4));
        }
        uint32_t b[4][2];
        #pragma unroll
        for (int p = 0; p < 2; ++p) {
            const int n = brow + p * 16;
            uint32_t r0, r1, r2, r3;
            ldsm_x4(r0, r1, r2, r3, Bs + n * 128 + ((g ^ (n & 7)) << 4));
            b[2*p][0] = r0; b[2*p+1][0] = r1; b[2*p][1] = r2; b[2*p+1][1] = r3;
        }
        #pragma unroll
        for (int t = 0; t < 2; ++t)
            #pragma unroll
            for (int q = 0; q < 4; ++q)
                mma16816(acc[t][q], a[t], b[q]);
    }
}

// 64x64 warp-tile chunk (joint kernel): 32 ldsm.x4 per 128 MMAs
__device__ __forceinline__ void mma_chunk64(uint32_t As, uint32_t Bs, int wm, int wn,
                                            int lane, float acc[4][8][4]) {
    const int arow = wm + (lane & 15);
    const int hi   = lane >> 4;
    const int brow = wn + ((lane >> 3) & 1) * 8 + (lane & 7);
    #pragma unroll
    for (int s = 0; s < 4; ++s) {
        const int g = s * 2 + hi;
        uint32_t a[4][4];
        #pragma unroll
        for (int t = 0; t < 4; ++t) {
            const int m = arow + t * 16;
            ldsm_x4(a[t][0], a[t][1], a[t][2], a[t][3], As + m * 128 + ((g ^ (m & 7)) << 4));
        }
        uint32_t b[8][2];
        #pragma unroll
        for (int p = 0; p < 4; ++p) {
            const int n = brow + p * 16;
            uint32_t r0, r1, r2, r3;
            ldsm_x4(r0, r1, r2, r3, Bs + n * 128 + ((g ^ (n & 7)) << 4));
            b[2*p][0] = r0; b[2*p+1][0] = r1; b[2*p][1] = r2; b[2*p+1][1] = r3;
        }
        #pragma unroll
        for (int t = 0; t < 4; ++t)
            #pragma unroll
            for (int q = 0; q < 8; ++q)
                mma16816(acc[t][q], a[t], b[q]);
    }
}

// ===================== transpose+cvt for enc/dec weights =====================
__global__ void __launch_bounds__(256)
transpose_cvt2_kernel(const float* __restrict__ in0, __half* __restrict__ out0,
                      const float* __restrict__ in1, __half* __restrict__ out1) {
    const float* in; __half* out; int R, C;
    if (blockIdx.z == 0) { in = in0; out = out0; R = EDIM; C = JDIM; }
    else                 { in = in1; out = out1; R = DDIM; C = JDIM; }
    const int bx = blockIdx.x * 64, by = blockIdx.y * 64;
    if (bx >= C || by >= R) return;
    __shared__ float tile[64][65];
    const int tid = threadIdx.x;
    const int tx = tid & 15, ty = tid >> 4;
    #pragma unroll
    for (int j = 0; j < 4; ++j) {
        const int r = ty + 16 * j;
        float4 v = __ldg(reinterpret_cast<const float4*>(in + (size_t)(by + r) * C + bx + tx * 4));
        tile[r][tx * 4 + 0] = v.x; tile[r][tx * 4 + 1] = v.y;
        tile[r][tx * 4 + 2] = v.z; tile[r][tx * 4 + 3] = v.w;
    }
    __syncthreads();
    #pragma unroll
    for (int j = 0; j < 4; ++j) {
        const int c = ty + 16 * j;
        uint2 o;
        o.x = pack_h2(tile[tx * 4 + 0][c], tile[tx * 4 + 1][c]);
        o.y = pack_h2(tile[tx * 4 + 2][c], tile[tx * 4 + 3][c]);
        *reinterpret_cast<uint2*>(out + (size_t)(bx + c) * R + by + tx * 4) = o;
    }
}

// ========== projection GEMMs + concurrent W_out transpose (one launch) ======
#define PJ_A0    0
#define PJ_B0    32768
#define PJ_BIAS  49152
#define PJ_SMEM  49408

__device__ __forceinline__ void pj_load_B(uint32_t Bs, const __half* __restrict__ WT,
                                          int n0, int K, int k0, int kv, int rb) {
    #pragma unroll
    for (int j = 0; j < 2; ++j) {
        const int n = rb + 32 * j;
        CP_ASYNC16(Bs + n * 128 + ((kv ^ (n & 7)) << 4),
                   WT + (size_t)(n0 + n) * K + k0 + kv * 8);
    }
}

__global__ void __launch_bounds__(256)
proj2_kernel(const float* __restrict__ Ae, const float* __restrict__ Ad,
             const float* __restrict__ be, const float* __restrict__ bd,
             const float* __restrict__ Wout) {
    extern __shared__ __align__(1024) char smem[];
    const uint32_t sb = smem_u32(smem);
    const int tid = threadIdx.x, wid = tid >> 5, lane = tid & 31;

    // ---- W_out transpose CTAs (concurrent with the projection GEMMs) ----
    if (blockIdx.x >= 12) {
        float (*tile)[65] = reinterpret_cast<float(*)[65]>(smem);
        const int bx = (blockIdx.x - 12) * 64;   // V col tile
        const int by = blockIdx.y * 64;          // J row tile
        const int tx = tid & 15, ty = tid >> 4;
        #pragma unroll
        for (int j = 0; j < 4; ++j) {
            const int r = ty + 16 * j;
            float4 v = __ldg(reinterpret_cast<const float4*>(
                Wout + (size_t)(by + r) * VDIM + bx + tx * 4));
            tile[r][tx * 4 + 0] = v.x; tile[r][tx * 4 + 1] = v.y;
            tile[r][tx * 4 + 2] = v.z; tile[r][tx * 4 + 3] = v.w;
        }
        __syncthreads();
        #pragma unroll
        for (int j = 0; j < 4; ++j) {
            const int c = ty + 16 * j;
            uint2 o;
            o.x = pack_h2(tile[tx * 4 + 0][c], tile[tx * 4 + 1][c]);
            o.y = pack_h2(tile[tx * 4 + 2][c], tile[tx * 4 + 3][c]);
            *reinterpret_cast<uint2*>(g_WoutT + (size_t)(bx + c) * JDIM + by + tx * 4) = o;
        }
        return;
    }

    // ---- projection GEMMs ----
    const bool is_enc = blockIdx.x < 8;
    const float* A    = is_enc ? Ae : Ad;
    const float* bias = is_enc ? be : bd;
    const __half* WT  = is_enc ? g_WencT : g_WdecT;
    __half* outp      = is_enc ? g_encp  : g_decp;
    const int K       = is_enc ? EDIM : DDIM;
    const int m0 = (is_enc ? blockIdx.x : blockIdx.x - 8) * 128;
    const int n0 = blockIdx.y * 64;
    const int kchunks = K >> 6;
    const int kv = tid & 7, rb = tid >> 3;

    if (tid < 16)
        reinterpret_cast<uint4*>(smem + PJ_BIAS)[tid] =
            __ldg(reinterpret_cast<const uint4*>(bias + n0) + tid);
    __syncthreads();

    float acc[2][4][4];
    #pragma unroll
    for (int t = 0; t < 2; ++t)
        #pragma unroll
        for (int q = 0; q < 4; ++q)
            #pragma unroll
            for (int v = 0; v < 4; ++v) acc[t][q][v] = 0.f;

    {
        char* As = smem + PJ_A0;
        #pragma unroll
        for (int i = 0; i < 4; ++i) {
            const int m = rb + 32 * i;
            const float* ap = A + (size_t)(m0 + m) * K + kv * 8;
            float4 a0 = __ldg(reinterpret_cast<const float4*>(ap));
            float4 a1 = __ldg(reinterpret_cast<const float4*>(ap + 4));
            uint4 r;
            r.x = pack_h2(a0.x, a0.y); r.y = pack_h2(a0.z, a0.w);
            r.z = pack_h2(a1.x, a1.y); r.w = pack_h2(a1.z, a1.w);
            *reinterpret_cast<uint4*>(As + m * 128 + ((kv ^ (m & 7)) << 4)) = r;
        }
        pj_load_B(sb + PJ_B0, WT, n0, K, 0, kv, rb);
        CP_COMMIT();
    }

    for (int c = 0; c < kchunks; ++c) {
        CP_WAIT0();
        __syncthreads();
        if (c + 1 < kchunks) {
            const int nb = (c + 1) & 1, k0 = (c + 1) * BK;
            char* As = smem + PJ_A0 + nb * 16384;
            #pragma unroll
            for (int i = 0; i < 4; ++i) {
                const int m = rb + 32 * i;
                const float* ap = A + (size_t)(m0 + m) * K + k0 + kv * 8;
                float4 a0 = __ldg(reinterpret_cast<const float4*>(ap));
                float4 a1 = __ldg(reinterpret_cast<const float4*>(ap + 4));
                uint4 r;
                r.x = pack_h2(a0.x, a0.y); r.y = pack_h2(a0.z, a0.w);
                r.z = pack_h2(a1.x, a1.y); r.w = pack_h2(a1.z, a1.w);
                *reinterpret_cast<uint4*>(As + m * 128 + ((kv ^ (m & 7)) << 4)) = r;
            }
            pj_load_B(sb + PJ_B0 + nb * 8192, WT, n0, K, k0, kv, rb);
            CP_COMMIT();
        }
        const int buf = c & 1;
        mma_chunk32(sb + PJ_A0 + buf * 16384, sb + PJ_B0 + buf * 8192,
                    (wid & 3) * 32, (wid >> 2) * 32, lane, acc);
    }

    const float* bs = reinterpret_cast<const float*>(smem + PJ_BIAS);
    const int wm = (wid & 3) * 32, wn = (wid >> 2) * 32;
    const int r0 = wm + (lane >> 2), c0 = wn + (lane & 3) * 2;
    __half* obase = outp + (size_t)m0 * JDIM + n0;
    #pragma unroll
    for (int t = 0; t < 2; ++t) {
        #pragma unroll
        for (int q = 0; q < 4; ++q) {
            const int col = c0 + q * 8;
            const float bx = bs[col], by = bs[col + 1];
            const int row = r0 + t * 16;
            __half2 lo = __floats2half2_rn(acc[t][q][0] + bx, acc[t][q][1] + by);
            __half2 hi = __floats2half2_rn(acc[t][q][2] + bx, acc[t][q][3] + by);
            *reinterpret_cast<__half2*>(obase + (size_t)row * JDIM + col) = lo;
            *reinterpret_cast<__half2*>(obase + (size_t)(row + 8) * JDIM + col) = hi;
        }
    }
}

// ============ fused joint: BM=128, BN=256, 64x64 warp tiles, 1 CTA/SM =================
// SMEM: A 8x16KB=131072 | B 2x32KB=65536 | enc 1KB | bias 4KB  => 201728 B
#define SM_A     0
#define SM_B     131072
#define SM_ENC   196608
#define SM_BIAS  197632
#define SMEM_JOINT 201728

__device__ __forceinline__ void load_Bv(uint32_t Bs, int v, int c, int kv, int rb) {
    #pragma unroll
    for (int j = 0; j < 8; ++j) {
        const int n = rb + 32 * j;
        CP_ASYNC16(Bs + n * 128 + ((kv ^ (n & 7)) << 4),
                   g_WoutT + (size_t)(v * 256 + n) * JDIM + c * BK + kv * 8);
    }
}

__global__ void __launch_bounds__(256, 1)
joint_kernel(const float* __restrict__ b_out, float* __restrict__ out) {
    extern __shared__ __align__(1024) char smem[];
    const uint32_t sb = smem_u32(smem);
    const int tid = threadIdx.x, wid = tid >> 5, lane = tid & 31;
    const int mb = blockIdx.x;               // b*T + t
    const int decrow0 = (mb >> 8) * UU;      // T = 256
    const int kv = tid & 7, rb = tid >> 3;   // rb: 0..31

    // first B-tile fetch immediately: overlaps the A-build below
    load_Bv(sb + SM_B, 0, 0, kv, rb);
    CP_COMMIT();
    int ldi = 1;

    if (tid < 64)
        reinterpret_cast<uint4*>(smem + SM_ENC)[tid] =
            __ldg(reinterpret_cast<const uint4*>(g_encp + (size_t)mb * JDIM) + tid);
    reinterpret_cast<uint4*>(smem + SM_BIAS)[tid] =
        __ldg(reinterpret_cast<const uint4*>(b_out) + tid);   // 256 uint4 = 1024 floats
    __syncthreads();
    const __half* encs = reinterpret_cast<const __half*>(smem + SM_ENC);

    // Build A = tanh(enc + dec): 8 slabs of 128 rows x 64 halves (16 KB each)
    #pragma unroll
    for (int c = 0; c < 8; ++c) {
        const uint4 ev = *reinterpret_cast<const uint4*>(encs + c * BK + kv * 8);
        char* As = smem + SM_A + c * 16384;
        #pragma unroll
        for (int i = 0; i < 4; ++i) {
            const int m = rb + 32 * i;
            uint4 dv = __ldg(reinterpret_cast<const uint4*>(
                g_decp + (size_t)(decrow0 + m) * JDIM + c * BK + kv * 8));
            uint4 r;
            r.x = tanh_add_h2(ev.x, dv.x); r.y = tanh_add_h2(ev.y, dv.y);
            r.z = tanh_add_h2(ev.z, dv.z); r.w = tanh_add_h2(ev.w, dv.w);
            *reinterpret_cast<uint4*>(As + m * 128 + ((kv ^ (m & 7)) << 4)) = r;
        }
    }
    __syncthreads();

    const int wm = (wid & 1) * 64, wn = (wid >> 1) * 64;
    const int r0 = wm + (lane >> 2), c0 = wn + (lane & 3) * 2;
    float* const obase0 = out + (size_t)mb * UU * VDIM;

    #pragma unroll 1
    for (int v = 0; v < 4; ++v) {
        float acc[4][8][4];
        #pragma unroll
        for (int t = 0; t < 4; ++t)
            #pragma unroll
            for (int q = 0; q < 8; ++q)
                #pragma unroll
                for (int x = 0; x < 4; ++x) acc[t][q][x] = 0.f;

        #pragma unroll 1
        for (int c = 0; c < 8; ++c) {
            CP_WAIT0();
            __syncthreads();
            if (ldi < 32) {
                load_Bv(sb + SM_B + (ldi & 1) * 32768, ldi >> 3, ldi & 7, kv, rb);
                CP_COMMIT();
                ++ldi;
            }
            mma_chunk64(sb + SM_A + c * 16384,
                        sb + SM_B + ((v * 8 + c) & 1) * 32768, wm, wn, lane, acc);
        }

        const float* bs = reinterpret_cast<const float*>(smem + SM_BIAS) + v * 256;
        float* obase = obase0 + v * 256;
        #pragma unroll
        for (int t = 0; t < 4; ++t) {
            #pragma unroll
            for (int q = 0; q < 8; ++q) {
                const int col = c0 + q * 8;
                const float bx = bs[col], by = bs[col + 1];
                const int row = r0 + t * 16;
                float2 lo = make_float2(acc[t][q][0] + bx, acc[t][q][1] + by);
                float2 hi = make_float2(acc[t][q][2] + bx, acc[t][q][3] + by);
                *reinterpret_cast<float2*>(obase + (size_t)row * VDIM + col) = lo;
                *reinterpret_cast<float2*>(obase + (size_t)(row + 8) * VDIM + col) = hi;
            }
        }
    }
}

extern "C" void kernel_launch(void* const* d_in, const int* in_sizes, int n_in,
                              void* d_out, int out_size) {
    const float* enc   = (const float*)d_in[0];
    const float* dec   = (const float*)d_in[1];
    const float* W_enc = (const float*)d_in[2];
    const float* b_enc = (const float*)d_in[3];
    const float* W_dec = (const float*)d_in[4];
    const float* b_dec = (const float*)d_in[5];
    const float* W_out = (const float*)d_in[6];
    const float* b_out = (const float*)d_in[7];
    float* out = (float*)d_out;

    cudaFuncSetAttribute(proj2_kernel, cudaFuncAttributeMaxDynamicSharedMemorySize, PJ_SMEM);
    cudaFuncSetAttribute(joint_kernel, cudaFuncAttributeMaxDynamicSharedMemorySize, SMEM_JOINT);

    __half *wencT, *wdecT;
    cudaGetSymbolAddress((void**)&wencT, g_WencT);
    cudaGetSymbolAddress((void**)&wdecT, g_WdecT);

    transpose_cvt2_kernel<<<dim3(8, 10, 2), 256>>>(W_enc, wencT, W_dec, wdecT);

    proj2_kernel<<<dim3(28, 8), 256, PJ_SMEM>>>(enc, dec, b_enc, b_dec, W_out);

    joint_kernel<<<BB * TT, 256, SMEM_JOINT>>>(b_out, out);
}

// round 14
// speedup vs baseline: 1.0205x; 1.0205x over previous
#include <cuda_runtime.h>
#include <cuda_fp16.h>
#include <cstdint>

#define BB    4
#define TT    256
#define UU    128
#define EDIM  512
#define DDIM  640
#define JDIM  512
#define VDIM  1024

#define BK 64

// scratch (__device__ globals; no allocation allowed)
__device__ __half g_encp [BB*TT*JDIM];
__device__ __half g_decp [BB*UU*JDIM];
__device__ __half g_WencT[JDIM*EDIM];
__device__ __half g_WdecT[JDIM*DDIM];
__device__ __half g_WoutT[VDIM*JDIM];

__device__ __forceinline__ uint32_t smem_u32(const void* p) {
    uint32_t a;
    asm("{ .reg .u64 t; cvta.to.shared.u64 t, %1; cvt.u32.u64 %0, t; }" : "=r"(a) : "l"(p));
    return a;
}
__device__ __forceinline__ void ldsm_x4(uint32_t& r0, uint32_t& r1, uint32_t& r2, uint32_t& r3,
                                        uint32_t a) {
    asm volatile("ldmatrix.sync.aligned.m8n8.x4.shared.b16 {%0,%1,%2,%3}, [%4];"
                 : "=r"(r0), "=r"(r1), "=r"(r2), "=r"(r3) : "r"(a));
}
__device__ __forceinline__ void mma16816(float* c, const uint32_t* a, const uint32_t* b) {
    asm volatile("mma.sync.aligned.m16n8k16.row.col.f32.f16.f16.f32 "
                 "{%0,%1,%2,%3}, {%4,%5,%6,%7}, {%8,%9}, {%0,%1,%2,%3};"
                 : "+f"(c[0]), "+f"(c[1]), "+f"(c[2]), "+f"(c[3])
                 : "r"(a[0]), "r"(a[1]), "r"(a[2]), "r"(a[3]), "r"(b[0]), "r"(b[1]));
}
#define CP_ASYNC16(dst, src) \
    asm volatile("cp.async.cg.shared.global [%0], [%1], 16;" :: "r"(dst), "l"(src) : "memory")
#define CP_COMMIT() asm volatile("cp.async.commit_group;" ::: "memory")
#define CP_WAIT0()  asm volatile("cp.async.wait_group 0;" ::: "memory")

__device__ __forceinline__ uint32_t pack_h2(float lo, float hi) {
    __half2 h = __floats2half2_rn(lo, hi);
    return reinterpret_cast<uint32_t&>(h);
}
__device__ __forceinline__ uint32_t tanh_add_h2(uint32_t a, uint32_t b) {
    __half2 s = __hadd2(reinterpret_cast<__half2&>(a), reinterpret_cast<__half2&>(b));
    uint32_t su = reinterpret_cast<uint32_t&>(s), r;
    asm("tanh.approx.f16x2 %0, %1;" : "=r"(r) : "r"(su));
    return r;
}

// 32x32 warp-tile chunk
__device__ __forceinline__ void mma_chunk32(uint32_t As, uint32_t Bs, int wm, int wn,
                                            int lane, float acc[2][4][4]) {
    const int arow = wm + (lane & 15);
    const int hi   = lane >> 4;
    const int brow = wn + ((lane >> 3) & 1) * 8 + (lane & 7);
    #pragma unroll
    for (int s = 0; s < 4; ++s) {
        const int g = s * 2 + hi;
        uint32_t a[2][4];
        #pragma unroll
        for (int t = 0; t < 2; ++t) {
            const int m = arow + t * 16;
            ldsm_x4(a[t][0], a[t][1], a[t][2], a[t][3], As + m * 128 + ((g ^ (m & 7)) << 4));
        }
        uint32_t b[4][2];
        #pragma unroll
        for (int p = 0; p < 2; ++p) {
            const int n = brow + p * 16;
            uint32_t r0, r1, r2, r3;
            ldsm_x4(r0, r1, r2, r3, Bs + n * 128 + ((g ^ (n & 7)) << 4));
            b[2*p][0] = r0; b[2*p+1][0] = r1; b[2*p][1] = r2; b[2*p+1][1] = r3;
        }
        #pragma unroll
        for (int t = 0; t < 2; ++t)
            #pragma unroll
            for (int q = 0; q < 4; ++q)
                mma16816(acc[t][q], a[t], b[q]);
    }
}

// ===================== transpose+cvt enc/dec weights: 144 CTAs, one wave ==============
__global__ void __launch_bounds__(256)
transpose_cvt2_kernel(const float* __restrict__ in0, __half* __restrict__ out0,
                      const float* __restrict__ in1, __half* __restrict__ out1) {
    int b = blockIdx.x;
    const float* in; __half* out; int R, C, bx, by;
    if (b < 64) { in = in0; out = out0; R = EDIM; C = JDIM; bx = (b & 7) * 64; by = (b >> 3) * 64; }
    else { b -= 64; in = in1; out = out1; R = DDIM; C = JDIM; bx = (b & 7) * 64; by = (b >> 3) * 64; }
    __shared__ float tile[64][65];
    const int tid = threadIdx.x;
    const int tx = tid & 15, ty = tid >> 4;
    #pragma unroll
    for (int j = 0; j < 4; ++j) {
        const int r = ty + 16 * j;
        float4 v = __ldg(reinterpret_cast<const float4*>(in + (size_t)(by + r) * C + bx + tx * 4));
        tile[r][tx * 4 + 0] = v.x; tile[r][tx * 4 + 1] = v.y;
        tile[r][tx * 4 + 2] = v.z; tile[r][tx * 4 + 3] = v.w;
    }
    __syncthreads();
    #pragma unroll
    for (int j = 0; j < 4; ++j) {
        const int c = ty + 16 * j;
        uint2 o;
        o.x = pack_h2(tile[tx * 4 + 0][c], tile[tx * 4 + 1][c]);
        o.y = pack_h2(tile[tx * 4 + 2][c], tile[tx * 4 + 3][c]);
        *reinterpret_cast<uint2*>(out + (size_t)(bx + c) * R + by + tx * 4) = o;
    }
}

// ===== projection GEMMs + concurrent W_out transpose (128x128 tiles), 128 CTAs =======
#define PJ_A0    0
#define PJ_B0    32768
#define PJ_BIAS  49152
#define PJ_SMEM  66048   // max(proj 49408, transpose 128*129*4)

__device__ __forceinline__ void pj_load_B(uint32_t Bs, const __half* __restrict__ WT,
                                          int n0, int K, int k0, int kv, int rb) {
    #pragma unroll
    for (int j = 0; j < 2; ++j) {
        const int n = rb + 32 * j;
        CP_ASYNC16(Bs + n * 128 + ((kv ^ (n & 7)) << 4),
                   WT + (size_t)(n0 + n) * K + k0 + kv * 8);
    }
}

__global__ void __launch_bounds__(256)
proj2_kernel(const float* __restrict__ Ae, const float* __restrict__ Ad,
             const float* __restrict__ be, const float* __restrict__ bd,
             const float* __restrict__ Wout) {
    extern __shared__ __align__(1024) char smem[];
    const uint32_t sb = smem_u32(smem);
    const int tid = threadIdx.x, wid = tid >> 5, lane = tid & 31;

    // ---- W_out transpose CTAs: 128(J) x 128(V) tiles, 4 x 8 = 32 CTAs ----
    if (blockIdx.x >= 12) {
        float (*tile)[129] = reinterpret_cast<float(*)[129]>(smem);
        const int by  = (blockIdx.x - 12) * 128;   // J row base
        const int bxv = blockIdx.y * 128;          // V col base
        const int tx = tid & 31, ty = tid >> 5;
        #pragma unroll
        for (int j = 0; j < 16; ++j) {
            const int r = ty + 8 * j;
            float4 v = __ldg(reinterpret_cast<const float4*>(
                Wout + (size_t)(by + r) * VDIM + bxv + tx * 4));
            tile[r][tx * 4 + 0] = v.x; tile[r][tx * 4 + 1] = v.y;
            tile[r][tx * 4 + 2] = v.z; tile[r][tx * 4 + 3] = v.w;
        }
        __syncthreads();
        #pragma unroll
        for (int j = 0; j < 16; ++j) {
            const int cc = ty + 8 * j;             // V index within tile
            uint2 o;
            o.x = pack_h2(tile[tx * 4 + 0][cc], tile[tx * 4 + 1][cc]);
            o.y = pack_h2(tile[tx * 4 + 2][cc], tile[tx * 4 + 3][cc]);
            *reinterpret_cast<uint2*>(g_WoutT + (size_t)(bxv + cc) * JDIM + by + tx * 4) = o;
        }
        return;
    }

    // ---- projection GEMMs ----
    const bool is_enc = blockIdx.x < 8;
    const float* A    = is_enc ? Ae : Ad;
    const float* bias = is_enc ? be : bd;
    const __half* WT  = is_enc ? g_WencT : g_WdecT;
    __half* outp      = is_enc ? g_encp  : g_decp;
    const int K       = is_enc ? EDIM : DDIM;
    const int m0 = (is_enc ? blockIdx.x : blockIdx.x - 8) * 128;
    const int n0 = blockIdx.y * 64;
    const int kchunks = K >> 6;
    const int kv = tid & 7, rb = tid >> 3;

    if (tid < 16)
        reinterpret_cast<uint4*>(smem + PJ_BIAS)[tid] =
            __ldg(reinterpret_cast<const uint4*>(bias + n0) + tid);
    __syncthreads();

    float acc[2][4][4];
    #pragma unroll
    for (int t = 0; t < 2; ++t)
        #pragma unroll
        for (int q = 0; q < 4; ++q)
            #pragma unroll
            for (int v = 0; v < 4; ++v) acc[t][q][v] = 0.f;

    {
        char* As = smem + PJ_A0;
        #pragma unroll
        for (int i = 0; i < 4; ++i) {
            const int m = rb + 32 * i;
            const float* ap = A + (size_t)(m0 + m) * K + kv * 8;
            float4 a0 = __ldg(reinterpret_cast<const float4*>(ap));
            float4 a1 = __ldg(reinterpret_cast<const float4*>(ap + 4));
            uint4 r;
            r.x = pack_h2(a0.x, a0.y); r.y = pack_h2(a0.z, a0.w);
            r.z = pack_h2(a1.x, a1.y); r.w = pack_h2(a1.z, a1.w);
            *reinterpret_cast<uint4*>(As + m * 128 + ((kv ^ (m & 7)) << 4)) = r;
        }
        pj_load_B(sb + PJ_B0, WT, n0, K, 0, kv, rb);
        CP_COMMIT();
    }

    for (int c = 0; c < kchunks; ++c) {
        CP_WAIT0();
        __syncthreads();
        if (c + 1 < kchunks) {
            const int nb = (c + 1) & 1, k0 = (c + 1) * BK;
            char* As = smem + PJ_A0 + nb * 16384;
            #pragma unroll
            for (int i = 0; i < 4; ++i) {
                const int m = rb + 32 * i;
                const float* ap = A + (size_t)(m0 + m) * K + k0 + kv * 8;
                float4 a0 = __ldg(reinterpret_cast<const float4*>(ap));
                float4 a1 = __ldg(reinterpret_cast<const float4*>(ap + 4));
                uint4 r;
                r.x = pack_h2(a0.x, a0.y); r.y = pack_h2(a0.z, a0.w);
                r.z = pack_h2(a1.x, a1.y); r.w = pack_h2(a1.z, a1.w);
                *reinterpret_cast<uint4*>(As + m * 128 + ((kv ^ (m & 7)) << 4)) = r;
            }
            pj_load_B(sb + PJ_B0 + nb * 8192, WT, n0, K, k0, kv, rb);
            CP_COMMIT();
        }
        const int buf = c & 1;
        mma_chunk32(sb + PJ_A0 + buf * 16384, sb + PJ_B0 + buf * 8192,
                    (wid & 3) * 32, (wid >> 2) * 32, lane, acc);
    }

    const float* bs = reinterpret_cast<const float*>(smem + PJ_BIAS);
    const int wm = (wid & 3) * 32, wn = (wid >> 2) * 32;
    const int r0 = wm + (lane >> 2), c0 = wn + (lane & 3) * 2;
    __half* obase = outp + (size_t)m0 * JDIM + n0;
    #pragma unroll
    for (int t = 0; t < 2; ++t) {
        #pragma unroll
        for (int q = 0; q < 4; ++q) {
            const int col = c0 + q * 8;
            const float bx = bs[col], by = bs[col + 1];
            const int row = r0 + t * 16;
            __half2 lo = __floats2half2_rn(acc[t][q][0] + bx, acc[t][q][1] + by);
            __half2 hi = __floats2half2_rn(acc[t][q][2] + bx, acc[t][q][3] + by);
            *reinterpret_cast<__half2*>(obase + (size_t)row * JDIM + col) = lo;
            *reinterpret_cast<__half2*>(obase + (size_t)(row + 8) * JDIM + col) = hi;
        }
    }
}

// ===================== fused joint: BM=64, 2 CTAs/SM, A-persistent (R12, 441us) =======
// SMEM: A 8x8KB=65536 | B 2x16KB=32768 | enc 1KB | bias 4KB  => 103424 B
#define SM_A     0
#define SM_B     65536
#define SM_ENC   98304
#define SM_BIAS  99328
#define SMEM_JOINT 103424

__device__ __forceinline__ void load_Bv(uint32_t Bs, int v, int c, int kv, int rb) {
    #pragma unroll
    for (int j = 0; j < 4; ++j) {
        const int n = rb + 32 * j;
        CP_ASYNC16(Bs + n * 128 + ((kv ^ (n & 7)) << 4),
                   g_WoutT + (size_t)(v * 128 + n) * JDIM + c * BK + kv * 8);
    }
}

__global__ void __launch_bounds__(256, 2)
joint_kernel(const float* __restrict__ b_out, float* __restrict__ out) {
    extern __shared__ __align__(1024) char smem[];
    const uint32_t sb = smem_u32(smem);
    const int tid = threadIdx.x, wid = tid >> 5, lane = tid & 31;
    const int mb = blockIdx.x >> 1;          // b*T + t
    const int uh = blockIdx.x & 1;           // u-half: rows uh*64 .. uh*64+63
    const int decrow0 = (mb >> 8) * UU + uh * 64;   // T = 256
    const int kv = tid & 7, rb = tid >> 3;   // rb: 0..31

    // first B-tile fetch immediately: overlaps the A-build below
    load_Bv(sb + SM_B, 0, 0, kv, rb);
    CP_COMMIT();
    int ldi = 1;

    if (tid < 64)
        reinterpret_cast<uint4*>(smem + SM_ENC)[tid] =
            __ldg(reinterpret_cast<const uint4*>(g_encp + (size_t)mb * JDIM) + tid);
    reinterpret_cast<uint4*>(smem + SM_BIAS)[tid] =
        __ldg(reinterpret_cast<const uint4*>(b_out) + tid);   // 256 uint4 = 1024 floats
    __syncthreads();
    const __half* encs = reinterpret_cast<const __half*>(smem + SM_ENC);

    // Build A = tanh(enc + dec): 8 slabs of 64 rows x 64 halves (8 KB each)
    #pragma unroll
    for (int c = 0; c < 8; ++c) {
        const uint4 ev = *reinterpret_cast<const uint4*>(encs + c * BK + kv * 8);
        char* As = smem + SM_A + c * 8192;
        #pragma unroll
        for (int i = 0; i < 2; ++i) {
            const int m = rb + 32 * i;
            uint4 dv = __ldg(reinterpret_cast<const uint4*>(
                g_decp + (size_t)(decrow0 + m) * JDIM + c * BK + kv * 8));
            uint4 r;
            r.x = tanh_add_h2(ev.x, dv.x); r.y = tanh_add_h2(ev.y, dv.y);
            r.z = tanh_add_h2(ev.z, dv.z); r.w = tanh_add_h2(ev.w, dv.w);
            *reinterpret_cast<uint4*>(As + m * 128 + ((kv ^ (m & 7)) << 4)) = r;
        }
    }
    __syncthreads();

    const int wm = (wid & 1) * 32, wn = (wid >> 1) * 32;
    const int r0 = wm + (lane >> 2), c0 = wn + (lane & 3) * 2;
    float* const obase0 = out + ((size_t)mb * UU + uh * 64) * VDIM;

    #pragma unroll 1
    for (int v = 0; v < 8; ++v) {
        float acc[2][4][4];
        #pragma unroll
        for (int t = 0; t < 2; ++t)
            #pragma unroll
            for (int q = 0; q < 4; ++q)
                #pragma unroll
                for (int x = 0; x < 4; ++x) acc[t][q][x] = 0.f;

        #pragma unroll 1
        for (int c = 0; c < 8; ++c) {
            CP_WAIT0();
            __syncthreads();
            if (ldi < 64) {
                load_Bv(sb + SM_B + (ldi & 1) * 16384, ldi >> 3, ldi & 7, kv, rb);
                CP_COMMIT();
                ++ldi;
            }
            mma_chunk32(sb + SM_A + c * 8192,
                        sb + SM_B + ((v * 8 + c) & 1) * 16384, wm, wn, lane, acc);
        }

        const float* bs = reinterpret_cast<const float*>(smem + SM_BIAS) + v * 128;
        float* obase = obase0 + v * 128;
        #pragma unroll
        for (int t = 0; t < 2; ++t) {
            #pragma unroll
            for (int q = 0; q < 4; ++q) {
                const int col = c0 + q * 8;
                const float bx = bs[col], by = bs[col + 1];
                const int row = r0 + t * 16;
                float2 lo = make_float2(acc[t][q][0] + bx, acc[t][q][1] + by);
                float2 hi = make_float2(acc[t][q][2] + bx, acc[t][q][3] + by);
                *reinterpret_cast<float2*>(obase + (size_t)row * VDIM + col) = lo;
                *reinterpret_cast<float2*>(obase + (size_t)(row + 8) * VDIM + col) = hi;
            }
        }
    }
}

extern "C" void kernel_launch(void* const* d_in, const int* in_sizes, int n_in,
                              void* d_out, int out_size) {
    const float* enc   = (const float*)d_in[0];
    const float* dec   = (const float*)d_in[1];
    const float* W_enc = (const float*)d_in[2];
    const float* b_enc = (const float*)d_in[3];
    const float* W_dec = (const float*)d_in[4];
    const float* b_dec = (const float*)d_in[5];
    const float* W_out = (const float*)d_in[6];
    const float* b_out = (const float*)d_in[7];
    float* out = (float*)d_out;

    cudaFuncSetAttribute(proj2_kernel, cudaFuncAttributeMaxDynamicSharedMemorySize, PJ_SMEM);
    cudaFuncSetAttribute(joint_kernel, cudaFuncAttributeMaxDynamicSharedMemorySize, SMEM_JOINT);

    __half *wencT, *wdecT;
    cudaGetSymbolAddress((void**)&wencT, g_WencT);
    cudaGetSymbolAddress((void**)&wdecT, g_WdecT);

    transpose_cvt2_kernel<<<144, 256>>>(W_enc, wencT, W_dec, wdecT);

    proj2_kernel<<<dim3(16, 8), 256, PJ_SMEM>>>(enc, dec, b_enc, b_dec, W_out);

    joint_kernel<<<2 * BB * TT, 256, SMEM_JOINT>>>(b_out, out);
}

// round 15
// speedup vs baseline: 1.0239x; 1.0033x over previous
#include <cuda_runtime.h>
#include <cuda_fp16.h>
#include <cstdint>

#define BB    4
#define TT    256
#define UU    128
#define EDIM  512
#define DDIM  640
#define JDIM  512
#define VDIM  1024

#define BK 64

// scratch (__device__ globals; no allocation allowed)
__device__ __half g_encp [BB*TT*JDIM];
__device__ __half g_decp [BB*UU*JDIM];
__device__ __half g_WencT[JDIM*EDIM];
__device__ __half g_WdecT[JDIM*DDIM];
__device__ __half g_WoutT[VDIM*JDIM];
__device__ unsigned g_bar = 0;   // monotonic grid-barrier counter (no reset needed)

__device__ __forceinline__ uint32_t smem_u32(const void* p) {
    uint32_t a;
    asm("{ .reg .u64 t; cvta.to.shared.u64 t, %1; cvt.u32.u64 %0, t; }" : "=r"(a) : "l"(p));
    return a;
}
__device__ __forceinline__ void ldsm_x4(uint32_t& r0, uint32_t& r1, uint32_t& r2, uint32_t& r3,
                                        uint32_t a) {
    asm volatile("ldmatrix.sync.aligned.m8n8.x4.shared.b16 {%0,%1,%2,%3}, [%4];"
                 : "=r"(r0), "=r"(r1), "=r"(r2), "=r"(r3) : "r"(a));
}
__device__ __forceinline__ void mma16816(float* c, const uint32_t* a, const uint32_t* b) {
    asm volatile("mma.sync.aligned.m16n8k16.row.col.f32.f16.f16.f32 "
                 "{%0,%1,%2,%3}, {%4,%5,%6,%7}, {%8,%9}, {%0,%1,%2,%3};"
                 : "+f"(c[0]), "+f"(c[1]), "+f"(c[2]), "+f"(c[3])
                 : "r"(a[0]), "r"(a[1]), "r"(a[2]), "r"(a[3]), "r"(b[0]), "r"(b[1]));
}
#define CP_ASYNC16(dst, src) \
    asm volatile("cp.async.cg.shared.global [%0], [%1], 16;" :: "r"(dst), "l"(src) : "memory")
#define CP_COMMIT() asm volatile("cp.async.commit_group;" ::: "memory")
#define CP_WAIT0()  asm volatile("cp.async.wait_group 0;" ::: "memory")

__device__ __forceinline__ uint32_t pack_h2(float lo, float hi) {
    __half2 h = __floats2half2_rn(lo, hi);
    return reinterpret_cast<uint32_t&>(h);
}
__device__ __forceinline__ uint32_t tanh_add_h2(uint32_t a, uint32_t b) {
    __half2 s = __hadd2(reinterpret_cast<__half2&>(a), reinterpret_cast<__half2&>(b));
    uint32_t su = reinterpret_cast<uint32_t&>(s), r;
    asm("tanh.approx.f16x2 %0, %1;" : "=r"(r) : "r"(su));
    return r;
}

// 32x32 warp-tile chunk
__device__ __forceinline__ void mma_chunk32(uint32_t As, uint32_t Bs, int wm, int wn,
                                            int lane, float acc[2][4][4]) {
    const int arow = wm + (lane & 15);
    const int hi   = lane >> 4;
    const int brow = wn + ((lane >> 3) & 1) * 8 + (lane & 7);
    #pragma unroll
    for (int s = 0; s < 4; ++s) {
        const int g = s * 2 + hi;
        uint32_t a[2][4];
        #pragma unroll
        for (int t = 0; t < 2; ++t) {
            const int m = arow + t * 16;
            ldsm_x4(a[t][0], a[t][1], a[t][2], a[t][3], As + m * 128 + ((g ^ (m & 7)) << 4));
        }
        uint32_t b[4][2];
        #pragma unroll
        for (int p = 0; p < 2; ++p) {
            const int n = brow + p * 16;
            uint32_t r0, r1, r2, r3;
            ldsm_x4(r0, r1, r2, r3, Bs + n * 128 + ((g ^ (n & 7)) << 4));
            b[2*p][0] = r0; b[2*p+1][0] = r1; b[2*p][1] = r2; b[2*p+1][1] = r3;
        }
        #pragma unroll
        for (int t = 0; t < 2; ++t)
            #pragma unroll
            for (int q = 0; q < 4; ++q)
                mma16816(acc[t][q], a[t], b[q]);
    }
}

// one 64x64 transpose+cvt tile through smem (phase-1 helper)
__device__ __forceinline__ void tr_tile(char* smem, const float* __restrict__ in,
                                        __half* __restrict__ out, int R, int C,
                                        int bx, int by, int tid) {
    float (*tile)[65] = reinterpret_cast<float(*)[65]>(smem);
    const int tx = tid & 15, ty = tid >> 4;
    #pragma unroll
    for (int j = 0; j < 4; ++j) {
        const int r = ty + 16 * j;
        float4 v = __ldg(reinterpret_cast<const float4*>(in + (size_t)(by + r) * C + bx + tx * 4));
        tile[r][tx * 4 + 0] = v.x; tile[r][tx * 4 + 1] = v.y;
        tile[r][tx * 4 + 2] = v.z; tile[r][tx * 4 + 3] = v.w;
    }
    __syncthreads();
    #pragma unroll
    for (int j = 0; j < 4; ++j) {
        const int c = ty + 16 * j;
        uint2 o;
        o.x = pack_h2(tile[tx * 4 + 0][c], tile[tx * 4 + 1][c]);
        o.y = pack_h2(tile[tx * 4 + 2][c], tile[tx * 4 + 3][c]);
        *reinterpret_cast<uint2*>(out + (size_t)(bx + c) * R + by + tx * 4) = o;
    }
    __syncthreads();
}

// ===== fused prologue: phase1 enc/dec W transpose -> grid barrier -> proj GEMMs + Wout
#define PJ_A0    0
#define PJ_B0    32768
#define PJ_BIAS  49152
#define PJ_SMEM  66048   // max(proj 49408, Wout transpose 128*129*4)
#define PJ_CTAS  128u

__device__ __forceinline__ void pj_load_B(uint32_t Bs, const __half* __restrict__ WT,
                                          int n0, int K, int k0, int kv, int rb) {
    #pragma unroll
    for (int j = 0; j < 2; ++j) {
        const int n = rb + 32 * j;
        CP_ASYNC16(Bs + n * 128 + ((kv ^ (n & 7)) << 4),
                   WT + (size_t)(n0 + n) * K + k0 + kv * 8);
    }
}

__global__ void __launch_bounds__(256)
proj2_kernel(const float* __restrict__ Ae, const float* __restrict__ Ad,
             const float* __restrict__ be, const float* __restrict__ bd,
             const float* __restrict__ We, const float* __restrict__ Wd,
             const float* __restrict__ Wout) {
    extern __shared__ __align__(1024) char smem[];
    const uint32_t sb = smem_u32(smem);
    const int tid = threadIdx.x, wid = tid >> 5, lane = tid & 31;
    const int bid = blockIdx.y * 16 + blockIdx.x;   // 0..127, all co-resident (one wave)

    // ---- phase 1: transpose+cvt W_enc (64 tiles) and W_dec (80 tiles) ----
    for (int t = bid; t < 144; t += 128) {
        if (t < 64)
            tr_tile(smem, We, g_WencT, EDIM, JDIM, (t & 7) * 64, (t >> 3) * 64, tid);
        else {
            const int l = t - 64;
            tr_tile(smem, Wd, g_WdecT, DDIM, JDIM, (l & 7) * 64, (l >> 3) * 64, tid);
        }
    }
    __threadfence();
    __syncthreads();
    if (tid == 0) {
        const unsigned old = atomicAdd(&g_bar, 1u);
        const unsigned target = (old / PJ_CTAS) * PJ_CTAS + PJ_CTAS;
        while (atomicAdd(&g_bar, 0u) < target) __nanosleep(32);
    }
    __syncthreads();

    // ---- phase 2a: W_out transpose CTAs (concurrent with proj GEMMs) ----
    if (blockIdx.x >= 12) {
        float (*tile)[129] = reinterpret_cast<float(*)[129]>(smem);
        const int by  = (blockIdx.x - 12) * 128;   // J row base
        const int bxv = blockIdx.y * 128;          // V col base
        const int tx = tid & 31, ty = tid >> 5;
        #pragma unroll
        for (int j = 0; j < 16; ++j) {
            const int r = ty + 8 * j;
            float4 v = __ldg(reinterpret_cast<const float4*>(
                Wout + (size_t)(by + r) * VDIM + bxv + tx * 4));
            tile[r][tx * 4 + 0] = v.x; tile[r][tx * 4 + 1] = v.y;
            tile[r][tx * 4 + 2] = v.z; tile[r][tx * 4 + 3] = v.w;
        }
        __syncthreads();
        #pragma unroll
        for (int j = 0; j < 16; ++j) {
            const int cc = ty + 8 * j;
            uint2 o;
            o.x = pack_h2(tile[tx * 4 + 0][cc], tile[tx * 4 + 1][cc]);
            o.y = pack_h2(tile[tx * 4 + 2][cc], tile[tx * 4 + 3][cc]);
            *reinterpret_cast<uint2*>(g_WoutT + (size_t)(bxv + cc) * JDIM + by + tx * 4) = o;
        }
        return;
    }

    // ---- phase 2b: projection GEMMs ----
    const bool is_enc = blockIdx.x < 8;
    const float* A    = is_enc ? Ae : Ad;
    const float* bias = is_enc ? be : bd;
    const __half* WT  = is_enc ? g_WencT : g_WdecT;
    __half* outp      = is_enc ? g_encp  : g_decp;
    const int K       = is_enc ? EDIM : DDIM;
    const int m0 = (is_enc ? blockIdx.x : blockIdx.x - 8) * 128;
    const int n0 = blockIdx.y * 64;
    const int kchunks = K >> 6;
    const int kv = tid & 7, rb = tid >> 3;

    if (tid < 16)
        reinterpret_cast<uint4*>(smem + PJ_BIAS)[tid] =
            __ldg(reinterpret_cast<const uint4*>(bias + n0) + tid);
    __syncthreads();

    float acc[2][4][4];
    #pragma unroll
    for (int t = 0; t < 2; ++t)
        #pragma unroll
        for (int q = 0; q < 4; ++q)
            #pragma unroll
            for (int v = 0; v < 4; ++v) acc[t][q][v] = 0.f;

    {
        char* As = smem + PJ_A0;
        #pragma unroll
        for (int i = 0; i < 4; ++i) {
            const int m = rb + 32 * i;
            const float* ap = A + (size_t)(m0 + m) * K + kv * 8;
            float4 a0 = __ldg(reinterpret_cast<const float4*>(ap));
            float4 a1 = __ldg(reinterpret_cast<const float4*>(ap + 4));
            uint4 r;
            r.x = pack_h2(a0.x, a0.y); r.y = pack_h2(a0.z, a0.w);
            r.z = pack_h2(a1.x, a1.y); r.w = pack_h2(a1.z, a1.w);
            *reinterpret_cast<uint4*>(As + m * 128 + ((kv ^ (m & 7)) << 4)) = r;
        }
        pj_load_B(sb + PJ_B0, WT, n0, K, 0, kv, rb);
        CP_COMMIT();
    }

    for (int c = 0; c < kchunks; ++c) {
        CP_WAIT0();
        __syncthreads();
        if (c + 1 < kchunks) {
            const int nb = (c + 1) & 1, k0 = (c + 1) * BK;
            char* As = smem + PJ_A0 + nb * 16384;
            #pragma unroll
            for (int i = 0; i < 4; ++i) {
                const int m = rb + 32 * i;
                const float* ap = A + (size_t)(m0 + m) * K + k0 + kv * 8;
                float4 a0 = __ldg(reinterpret_cast<const float4*>(ap));
                float4 a1 = __ldg(reinterpret_cast<const float4*>(ap + 4));
                uint4 r;
                r.x = pack_h2(a0.x, a0.y); r.y = pack_h2(a0.z, a0.w);
                r.z = pack_h2(a1.x, a1.y); r.w = pack_h2(a1.z, a1.w);
                *reinterpret_cast<uint4*>(As + m * 128 + ((kv ^ (m & 7)) << 4)) = r;
            }
            pj_load_B(sb + PJ_B0 + nb * 8192, WT, n0, K, k0, kv, rb);
            CP_COMMIT();
        }
        const int buf = c & 1;
        mma_chunk32(sb + PJ_A0 + buf * 16384, sb + PJ_B0 + buf * 8192,
                    (wid & 3) * 32, (wid >> 2) * 32, lane, acc);
    }

    const float* bs = reinterpret_cast<const float*>(smem + PJ_BIAS);
    const int wm = (wid & 3) * 32, wn = (wid >> 2) * 32;
    const int r0 = wm + (lane >> 2), c0 = wn + (lane & 3) * 2;
    __half* obase = outp + (size_t)m0 * JDIM + n0;
    #pragma unroll
    for (int t = 0; t < 2; ++t) {
        #pragma unroll
        for (int q = 0; q < 4; ++q) {
            const int col = c0 + q * 8;
            const float bx = bs[col], by = bs[col + 1];
            const int row = r0 + t * 16;
            __half2 lo = __floats2half2_rn(acc[t][q][0] + bx, acc[t][q][1] + by);
            __half2 hi = __floats2half2_rn(acc[t][q][2] + bx, acc[t][q][3] + by);
            *reinterpret_cast<__half2*>(obase + (size_t)row * JDIM + col) = lo;
            *reinterpret_cast<__half2*>(obase + (size_t)(row + 8) * JDIM + col) = hi;
        }
    }
}

// ===================== fused joint: BM=64, 2 CTAs/SM, A-persistent (R12, 441us) =======
// SMEM: A 8x8KB=65536 | B 2x16KB=32768 | enc 1KB | bias 4KB  => 103424 B
#define SM_A     0
#define SM_B     65536
#define SM_ENC   98304
#define SM_BIAS  99328
#define SMEM_JOINT 103424

__device__ __forceinline__ void load_Bv(uint32_t Bs, int v, int c, int kv, int rb) {
    #pragma unroll
    for (int j = 0; j < 4; ++j) {
        const int n = rb + 32 * j;
        CP_ASYNC16(Bs + n * 128 + ((kv ^ (n & 7)) << 4),
                   g_WoutT + (size_t)(v * 128 + n) * JDIM + c * BK + kv * 8);
    }
}

__global__ void __launch_bounds__(256, 2)
joint_kernel(const float* __restrict__ b_out, float* __restrict__ out) {
    extern __shared__ __align__(1024) char smem[];
    const uint32_t sb = smem_u32(smem);
    const int tid = threadIdx.x, wid = tid >> 5, lane = tid & 31;
    const int mb = blockIdx.x >> 1;          // b*T + t
    const int uh = blockIdx.x & 1;           // u-half: rows uh*64 .. uh*64+63
    const int decrow0 = (mb >> 8) * UU + uh * 64;   // T = 256
    const int kv = tid & 7, rb = tid >> 3;   // rb: 0..31

    // first B-tile fetch immediately: overlaps the A-build below
    load_Bv(sb + SM_B, 0, 0, kv, rb);
    CP_COMMIT();
    int ldi = 1;

    if (tid < 64)
        reinterpret_cast<uint4*>(smem + SM_ENC)[tid] =
            __ldg(reinterpret_cast<const uint4*>(g_encp + (size_t)mb * JDIM) + tid);
    reinterpret_cast<uint4*>(smem + SM_BIAS)[tid] =
        __ldg(reinterpret_cast<const uint4*>(b_out) + tid);   // 256 uint4 = 1024 floats
    __syncthreads();
    const __half* encs = reinterpret_cast<const __half*>(smem + SM_ENC);

    // Build A = tanh(enc + dec): 8 slabs of 64 rows x 64 halves (8 KB each)
    #pragma unroll
    for (int c = 0; c < 8; ++c) {
        const uint4 ev = *reinterpret_cast<const uint4*>(encs + c * BK + kv * 8);
        char* As = smem + SM_A + c * 8192;
        #pragma unroll
        for (int i = 0; i < 2; ++i) {
            const int m = rb + 32 * i;
            uint4 dv = __ldg(reinterpret_cast<const uint4*>(
                g_decp + (size_t)(decrow0 + m) * JDIM + c * BK + kv * 8));
            uint4 r;
            r.x = tanh_add_h2(ev.x, dv.x); r.y = tanh_add_h2(ev.y, dv.y);
            r.z = tanh_add_h2(ev.z, dv.z); r.w = tanh_add_h2(ev.w, dv.w);
            *reinterpret_cast<uint4*>(As + m * 128 + ((kv ^ (m & 7)) << 4)) = r;
        }
    }
    __syncthreads();

    const int wm = (wid & 1) * 32, wn = (wid >> 1) * 32;
    const int r0 = wm + (lane >> 2), c0 = wn + (lane & 3) * 2;
    float* const obase0 = out + ((size_t)mb * UU + uh * 64) * VDIM;

    #pragma unroll 1
    for (int v = 0; v < 8; ++v) {
        float acc[2][4][4];
        #pragma unroll
        for (int t = 0; t < 2; ++t)
            #pragma unroll
            for (int q = 0; q < 4; ++q)
                #pragma unroll
                for (int x = 0; x < 4; ++x) acc[t][q][x] = 0.f;

        #pragma unroll 1
        for (int c = 0; c < 8; ++c) {
            CP_WAIT0();
            __syncthreads();
            if (ldi < 64) {
                load_Bv(sb + SM_B + (ldi & 1) * 16384, ldi >> 3, ldi & 7, kv, rb);
                CP_COMMIT();
                ++ldi;
            }
            mma_chunk32(sb + SM_A + c * 8192,
                        sb + SM_B + ((v * 8 + c) & 1) * 16384, wm, wn, lane, acc);
        }

        const float* bs = reinterpret_cast<const float*>(smem + SM_BIAS) + v * 128;
        float* obase = obase0 + v * 128;
        #pragma unroll
        for (int t = 0; t < 2; ++t) {
            #pragma unroll
            for (int q = 0; q < 4; ++q) {
                const int col = c0 + q * 8;
                const float bx = bs[col], by = bs[col + 1];
                const int row = r0 + t * 16;
                float2 lo = make_float2(acc[t][q][0] + bx, acc[t][q][1] + by);
                float2 hi = make_float2(acc[t][q][2] + bx, acc[t][q][3] + by);
                *reinterpret_cast<float2*>(obase + (size_t)row * VDIM + col) = lo;
                *reinterpret_cast<float2*>(obase + (size_t)(row + 8) * VDIM + col) = hi;
            }
        }
    }
}

extern "C" void kernel_launch(void* const* d_in, const int* in_sizes, int n_in,
                              void* d_out, int out_size) {
    const float* enc   = (const float*)d_in[0];
    const float* dec   = (const float*)d_in[1];
    const float* W_enc = (const float*)d_in[2];
    const float* b_enc = (const float*)d_in[3];
    const float* W_dec = (const float*)d_in[4];
    const float* b_dec = (const float*)d_in[5];
    const float* W_out = (const float*)d_in[6];
    const float* b_out = (const float*)d_in[7];
    float* out = (float*)d_out;

    cudaFuncSetAttribute(proj2_kernel, cudaFuncAttributeMaxDynamicSharedMemorySize, PJ_SMEM);
    cudaFuncSetAttribute(joint_kernel, cudaFuncAttributeMaxDynamicSharedMemorySize, SMEM_JOINT);

    proj2_kernel<<<dim3(16, 8), 256, PJ_SMEM>>>(enc, dec, b_enc, b_dec, W_enc, W_dec, W_out);

    joint_kernel<<<2 * BB * TT, 256, SMEM_JOINT>>>(b_out, out);
}